// round 14
// baseline (speedup 1.0000x reference)
#include <cuda_runtime.h>
#include <cuda_bf16.h>
#include <cstdint>

// ---------------------------------------------------------------------------
// EdgeAlignmentModule — single fused kernel, generation-tagged hash join,
// ONE software grid barrier, no reset, no cleanup.
//
//   key(src,dst) = src * total_nodes + dst   (< 1e8, fits in 27 bits)
//   Slot word (64b) = gen(18) << 46 | key(27) << 19 | idx(19)
//
// Slot with gen field != current gen is EMPTY (stale); claimed by CAS against
// the observed stale word. Duplicate keys within a call -> MAX old index
// (== sequential-scatter "last wins" of table.at[old_keys].set(arange)) via
// atomicMax (equal gen|key orders by idx).
//
// Per-call generation AND barrier target derive from one monotonic counter:
// each block bumps it once; call = t / NBLOCKS (stream ordering partitions
// arrivals per call), gen = call + 1, barrier release when the monotonic
// arrive counter reaches (call+1)*NBLOCKS. Nothing is ever reset -> every
// graph replay is identical work. Table starts zeroed (gen 0 = stale).
//
// Deadlock safety: NBLOCKS = 1184 = 8 blocks/SM x 148 SMs, and
// __launch_bounds__(256, 8) forces the register budget that guarantees 8
// co-resident blocks/SM, so all blocks run concurrently at the barrier.
//
// Overlap: each thread issues its lookup-side independent loads (new edge
// indices + new attrs) BEFORE arriving at the barrier; they complete while
// waiting, so post-barrier work starts at the probe.
// ---------------------------------------------------------------------------

#define TABLE_LOG2 20
#define TABLE_SIZE (1u << TABLE_LOG2)
#define TABLE_MASK (TABLE_SIZE - 1u)

#define GEN_SHIFT 46
#define KEY_SHIFT 19
#define IDX_MASK  ((1u << KEY_SHIFT) - 1u)

#define NTHREADS 256
#define NBLOCKS  1184              // 8 blocks/SM * 148 SMs (co-resident)
#define STRIDE   (NBLOCKS * NTHREADS)
#define E_OLD_MAX 400000

__device__ unsigned long long g_tab[TABLE_SIZE];   // zero-init: gen 0 = stale
__device__ float4 g_packed[E_OLD_MAX];             // [ea0,ea1,ea2,flow] per old edge
__device__ unsigned long long g_call_ctr;          // monotonic: one bump per block
__device__ unsigned long long g_bar_ctr;           // monotonic barrier arrivals

__device__ __forceinline__ uint32_t hash_key(uint32_t key) {
    return (key * 0x9E3779B1u) >> (32 - TABLE_LOG2);
}

__global__ __launch_bounds__(NTHREADS, 8)
void edge_align_fused(const int*   __restrict__ edge_index_old,
                      const float* __restrict__ edge_attr_old,
                      const float* __restrict__ flow_old,
                      const int*   __restrict__ edge_index_new,
                      const float* __restrict__ edge_attr_new,
                      float*       __restrict__ out,
                      int E_old, int E_new, int total_nodes) {
    __shared__ unsigned long long s_gen;
    __shared__ unsigned long long s_target;
    if (threadIdx.x == 0) {
        unsigned long long t = atomicAdd(&g_call_ctr, 1ull);
        unsigned long long call = t / NBLOCKS;     // same for all blocks of a call
        s_gen = call + 1ull;
        s_target = (call + 1ull) * NBLOCKS;        // barrier release threshold
    }
    __syncthreads();
    const unsigned long long gen = s_gen;
    const int t = blockIdx.x * NTHREADS + threadIdx.x;

    // ---- Phase 1: insert old edges + pack features (grid-stride) ----
    for (int i = t; i < E_old; i += STRIDE) {
        int src = __ldg(edge_index_old + i);
        int dst = __ldg(edge_index_old + E_old + i);
        const float* ea = edge_attr_old + (size_t)i * 3;
        float f0 = __ldg(ea + 0);
        float f1 = __ldg(ea + 1);
        float f2 = __ldg(ea + 2);
        float f3 = __ldg(flow_old + i);
        g_packed[i] = make_float4(f0, f1, f2, f3);

        uint32_t key = (uint32_t)(src * total_nodes + dst);
        const unsigned long long word =
            (gen << GEN_SHIFT) | ((unsigned long long)key << KEY_SHIFT)
            | (unsigned long long)(uint32_t)i;

        uint32_t h = hash_key(key);
        unsigned long long w = g_tab[h];
        while (true) {
            if ((w >> GEN_SHIFT) != gen) {
                unsigned long long prev = atomicCAS(&g_tab[h], w, word);
                if (prev == w) break;              // claimed (value rides along)
                w = prev;                          // re-examine what beat us
            } else if (((w >> KEY_SHIFT) & 0x7FFFFFFull) == key) {
                atomicMax(&g_tab[h], word);        // duplicate key: max idx wins
                break;
            } else {
                h = (h + 1) & TABLE_MASK;
                w = g_tab[h];
            }
        }
    }

    // ---- Lookup prologue: table-independent loads, issued pre-barrier ----
    int i0 = t;
    bool v0 = (i0 < E_new);
    uint32_t key0 = 0, h0 = 0;
    float n0 = 0.f, n1 = 0.f, n2 = 0.f;
    if (v0) {
        int src = __ldg(edge_index_new + i0);
        int dst = __ldg(edge_index_new + E_new + i0);
        const float* en = edge_attr_new + (size_t)i0 * 3;
        n0 = __ldg(en + 0); n1 = __ldg(en + 1); n2 = __ldg(en + 2);
        key0 = (uint32_t)(src * total_nodes + dst);
        h0 = hash_key(key0);
    }

    // ---- ONE grid barrier (monotonic counter, nanosleep backoff) ----
    __syncthreads();                       // whole block finished inserting
    if (threadIdx.x == 0) {
        __threadfence();                   // publish g_packed + table words
        atomicAdd(&g_bar_ctr, 1ull);
        unsigned long long tgt = s_target;
        while (true) {
            unsigned long long c =
                atomicAdd(&g_bar_ctr, 0ull);   // coherent read
            if (c >= tgt) break;
            __nanosleep(128);
        }
        __threadfence();                   // acquire
    }
    __syncthreads();

    // ---- Phase 2: probe + gather + emit ----
    if (v0) {
        int match = -1;
        uint32_t h = h0;
        while (true) {
            unsigned long long w = __ldg(&g_tab[h]);
            if ((w >> GEN_SHIFT) != gen) break;            // empty: miss
            if (((w >> KEY_SHIFT) & 0x7FFFFFFull) == key0) {
                match = (int)(w & IDX_MASK);
                break;
            }
            h = (h + 1) & TABLE_MASK;
        }
        float4 a = make_float4(0.f, 0.f, 0.f, 0.f);
        float flag = 1.f;
        if (match >= 0) { a = g_packed[match]; flag = 0.f; }
        float4* o = reinterpret_cast<float4*>(out + (size_t)i0 * 8);
        o[0] = a;
        o[1] = make_float4(n0, n1, n2, flag);
    }
    // Remaining grid-stride edges (only ~5% of threads have one).
    for (int i = t + STRIDE; i < E_new; i += STRIDE) {
        int src = __ldg(edge_index_new + i);
        int dst = __ldg(edge_index_new + E_new + i);
        const float* en = edge_attr_new + (size_t)i * 3;
        float m0 = __ldg(en + 0), m1 = __ldg(en + 1), m2 = __ldg(en + 2);
        uint32_t key = (uint32_t)(src * total_nodes + dst);

        int match = -1;
        uint32_t h = hash_key(key);
        while (true) {
            unsigned long long w = __ldg(&g_tab[h]);
            if ((w >> GEN_SHIFT) != gen) break;
            if (((w >> KEY_SHIFT) & 0x7FFFFFFull) == key) {
                match = (int)(w & IDX_MASK);
                break;
            }
            h = (h + 1) & TABLE_MASK;
        }
        float4 a = make_float4(0.f, 0.f, 0.f, 0.f);
        float flag = 1.f;
        if (match >= 0) { a = g_packed[match]; flag = 0.f; }
        float4* o = reinterpret_cast<float4*>(out + (size_t)i * 8);
        o[0] = a;
        o[1] = make_float4(m0, m1, m2, flag);
    }
}

extern "C" void kernel_launch(void* const* d_in, const int* in_sizes, int n_in,
                              void* d_out, int out_size) {
    const int*   edge_index_old = (const int*)  d_in[0];
    const float* edge_attr_old  = (const float*)d_in[1];
    const float* flow_old       = (const float*)d_in[2];
    const int*   edge_index_new = (const int*)  d_in[3];
    const float* edge_attr_new  = (const float*)d_in[4];
    (void)n_in; (void)out_size;

    int E_old = in_sizes[1] / 3;   // edge_attr_old is [E_old, 3]
    int E_new = in_sizes[4] / 3;   // edge_attr_new is [E_new, 3]
    int total_nodes = 10000;       // fixed by problem; key fits in 27 bits

    edge_align_fused<<<NBLOCKS, NTHREADS>>>(
        edge_index_old, edge_attr_old, flow_old,
        edge_index_new, edge_attr_new, (float*)d_out,
        E_old, E_new, total_nodes);
}